// round 12
// baseline (speedup 1.0000x reference)
#include <cuda_runtime.h>
#include <cuda_fp16.h>
#include <cstdint>

// Fixed problem shapes
#define BB    16
#define DC    16
#define ND    1024
#define CIN   64
#define COUT  128
#define NN    4096
#define KW    7
#define LT    64             // l-tile per CTA
#define NCH   8              // K chunks (8 channels each)
#define NTHR  512            // 16 warps, all do build + MMA

// Scratch (device globals; no allocation allowed)
__device__ float g_z[BB*CIN*ND];
__device__ float g_scale[BB*CIN];
__device__ float g_shift[BB*CIN];
__device__ __align__(16) __half g_wH[NCH*COUT*64];   // [ch][o][col], col=cc*8+k

// ---------------- smem layout (bytes) ----------------
#define ROWB   144                    // 64 fp16 cols padded to 72 -> conflict-free ldmatrix
#define OFF_XY   0                    // sxr: 64 ch x 72 uint2 = 36864  (r1,r2 | r3,x as half4)
#define OFF_ST   36864
#define T_W      0                    // 128 o rows x 144B = 18432
#define T_M      18432                // 64 l rows x 144B  = 9216
#define STAGE_BYTES 27648
#define OFF_TMP  (OFF_ST + 18432)     // temp (x,xs) float2: 36864B, dies before build(0)
#define SMEM_TOTAL (OFF_ST + 2*STAGE_BYTES)   // 92160 -> 2 CTAs/SM

#define CP16(dst, src) asm volatile("cp.async.cg.shared.global [%0], [%1], 16;" :: "r"(dst), "l"(src) : "memory")
#define CPCOMMIT()     asm volatile("cp.async.commit_group;" ::: "memory")
#define CPWAIT0()      asm volatile("cp.async.wait_group 0;" ::: "memory")

__device__ __forceinline__ uint32_t smem_u32(const void* p) {
    uint32_t a;
    asm("{ .reg .u64 t; cvta.to.shared.u64 t, %1; cvt.u32.u64 %0, t; }" : "=r"(a) : "l"(p));
    return a;
}
__device__ __forceinline__ float rcpa(float x) {
    float r;
    asm("rcp.approx.f32 %0, %1;" : "=f"(r) : "f"(x));
    return r;
}
// pack(first, second) -> f16x2, first in bits[15:0]
__device__ __forceinline__ uint32_t packh(float a0, float a1) {
    uint32_t r;
    asm("cvt.rn.f16x2.f32 %0, %1, %2;" : "=r"(r) : "f"(a1), "f"(a0));
    return r;
}
__device__ __forceinline__ float lo2f(uint32_t v) {   // low half -> float
    return __low2float(*(const __half2*)&v);
}
__device__ __forceinline__ float hi2f(uint32_t v) {   // high half -> float
    return __high2float(*(const __half2*)&v);
}
#define LDSM4(r, a) \
    asm volatile("ldmatrix.sync.aligned.m8n8.x4.shared.b16 {%0,%1,%2,%3}, [%4];" \
        : "=r"((r)[0]), "=r"((r)[1]), "=r"((r)[2]), "=r"((r)[3]) : "r"(a))
#define MMAH(d, a, b0, b1) \
    asm volatile("mma.sync.aligned.m16n8k16.row.col.f32.f16.f16.f32 " \
        "{%0,%1,%2,%3},{%4,%5,%6,%7},{%8,%9},{%0,%1,%2,%3};" \
        : "+f"((d)[0]), "+f"((d)[1]), "+f"((d)[2]), "+f"((d)[3]) \
        : "r"((a)[0]), "r"((a)[1]), "r"((a)[2]), "r"((a)[3]), "r"(b0), "r"(b1))

// ---------------- kernel 1: fused z + stats + wsplit ----------------
__global__ void k_prep(const float* __restrict__ deep, const float* __restrict__ conv_w,
                       const float* __restrict__ conv_b, const float* __restrict__ fc_w) {
    __shared__ float sz[ND];
    __shared__ float cw[DC];
    __shared__ float red1[8], red2[8];
    int bc  = blockIdx.x;
    int c   = bc & (CIN-1);
    int b   = bc >> 6;
    int tid = threadIdx.x;
    if (tid < 64) {
        int idx = bc*64 + tid;
        int ch  = idx >> 13;
        int o   = (idx >> 6) & 127;
        int col = idx & 63;
        int cc = col >> 3, k = col & 7;
        float v = (k < KW) ? fc_w[o*(CIN*KW) + (ch*8 + cc)*KW + k] : 0.f;
        g_wH[idx] = __float2half_rn(v);
    }
    if (tid < DC) cw[tid] = conv_w[c*DC + tid];
    __syncthreads();
    const float* dp = deep + (size_t)b*DC*ND;
    float* zrow = g_z + (size_t)bc*ND;
    for (int m = tid; m < ND; m += 256) {
        float acc = 0.f;
        #pragma unroll
        for (int d = 0; d < DC; ++d) acc += cw[d] * dp[(size_t)d*ND + m];
        sz[m] = acc;
        zrow[m] = acc;
    }
    __syncthreads();
    float bias = conv_b[c];
    float s1 = 0.f, s2 = 0.f;
    for (int n = tid; n < NN; n += 256) {
        float src = 0.25f*(float)n - 0.375f;
        src = fminf(fmaxf(src, 0.f), (float)(ND-1));
        int lo = (int)src;
        int hi = min(lo + 1, ND-1);
        float w = src - (float)lo;
        float v = sz[lo]*(1.f - w) + sz[hi]*w + bias;
        s1 += v; s2 += v*v;
    }
    #pragma unroll
    for (int off = 16; off; off >>= 1) {
        s1 += __shfl_down_sync(0xffffffffu, s1, off);
        s2 += __shfl_down_sync(0xffffffffu, s2, off);
    }
    if ((tid & 31) == 0) { red1[tid>>5] = s1; red2[tid>>5] = s2; }
    __syncthreads();
    if (tid == 0) {
        float t1 = 0.f, t2 = 0.f;
        #pragma unroll
        for (int i = 0; i < 8; ++i) { t1 += red1[i]; t2 += red2[i]; }
        float mean = t1 / (float)NN;
        float var  = (t2 - (float)NN*mean*mean) / (float)(NN-1);
        float sc   = 0.5f / (var + 1e-9f);
        g_scale[bc] = sc;
        g_shift[bc] = -sc * mean;
    }
}

// r(d) = u/(1+u)^2, u = exp(-2d); tap3's 1/4 factor folded in normalization
__device__ __forceinline__ float rtap(float xa, float xb) {
    float u = __expf(-2.0f * fabsf(xa - xb));
    float v = 1.0f + u;
    return u * rcpa(v * v);
}

// ---------------- build one chunk's m tile: no transcendentals ----------------
__device__ __forceinline__ void build_m(char* stage, int ch, int tid, const uint2* sxr) {
    int l  = tid & 63;
    int cc = tid >> 6;                  // 0..7
    const uint2* qp = sxr + (ch*8 + cc)*72 + l;
    uint2 q0 = qp[0], q1 = qp[1], q2 = qp[2], q3 = qp[3], q4 = qp[4], q5 = qp[5], q6 = qp[6];
    // q.x = half2(r1, r2); q.y = half2(r3, x)
    float s0 = lo2f(q0.y);              // r3(l)
    float s1 = hi2f(q1.x);              // r2(l+1)
    float s2 = lo2f(q2.x);              // r1(l+2)
    float s4 = lo2f(q3.x);              // r1(l+3)
    float s5 = hi2f(q3.x);              // r2(l+3)
    float s6 = lo2f(q3.y);              // r3(l+3)
    float den = ((s0 + s1) + (s2 + 0.25f)) + ((s4 + s5) + s6);
    float inv = rcpa(den);
    float m0 = (hi2f(q0.y) * s0) * inv;
    float m1 = (hi2f(q1.y) * s1) * inv;
    float m2 = (hi2f(q2.y) * s2) * inv;
    float m3 = hi2f(q3.y) * (0.25f * inv);
    float m4 = (hi2f(q4.y) * s4) * inv;
    float m5 = (hi2f(q5.y) * s5) * inv;
    float m6 = (hi2f(q6.y) * s6) * inv;
    uint32_t h0 = packh(m0, m1), h1 = packh(m2, m3), h2 = packh(m4, m5), h3 = packh(m6, 0.f);
    *(uint4*)(stage + T_M + l*ROWB + cc*16) = make_uint4(h0, h1, h2, h3);
}

__device__ __forceinline__ void load_w(uint32_t st, int ch, int tid) {
    const char* src = (const char*)(g_wH + (size_t)ch*COUT*64);
    #pragma unroll
    for (int j = 0; j < 2; ++j) {
        int idx = tid + j*NTHR;
        int o = idx >> 3, seg = idx & 7;
        CP16(st + T_W + (uint32_t)(o*ROWB + seg*16), src + (size_t)idx*16);
    }
    CPCOMMIT();
}

// ---------------- kernel 2: all-hands fused build + HMMA GEMM ----------------
// grid (NN/LT=64, BB=16) = 1024 CTAs, 512 threads, 2 CTAs/SM (32 warps/SM).
__global__ __launch_bounds__(NTHR, 2)
void k_tc(const float* __restrict__ x, const float* __restrict__ conv_b,
          float* __restrict__ out) {
    extern __shared__ __align__(16) char smem[];
    const uint32_t sb = smem_u32(smem);
    const int tid  = threadIdx.x;
    const int lane = tid & 31;
    const int wid  = tid >> 5;
    const int b    = blockIdx.y;
    const int l0   = blockIdx.x * LT;

    uint2*  sxr  = (uint2*) (smem + OFF_XY);
    float2* temp = (float2*)(smem + OFF_TMP);

    load_w(sb + OFF_ST, 0, tid);        // W0 -> stage 0 (async)

    // ---- pass 1: stage (x, xs) fp32 into temp, 64 ch x 70 positions ----
    #pragma unroll 2
    for (int t = tid; t < CIN*70; t += NTHR) {
        int c = t / 70, i = t - c*70;
        int p = l0 - 3 + i;
        if (p < 0)   p = -p;
        if (p >= NN) p = 2*NN - 2 - p;
        int bc = b*CIN + c;
        float src = 0.25f*(float)p - 0.375f;
        src = fminf(fmaxf(src, 0.f), (float)(ND-1));
        int lo = (int)src;
        int hi = min(lo + 1, ND-1);
        float w = src - (float)lo;
        const float* zrow = g_z + (size_t)bc*ND;
        float v = zrow[lo]*(1.f - w) + zrow[hi]*w + conv_b[c];
        temp[c*72 + i] = make_float2(x[(size_t)bc*NN + p],
                                     g_scale[bc] * v + g_shift[bc]);
    }
    __syncthreads();

    // ---- pass 2: precompute r1,r2,r3 + x -> half4 sxr ----
    #pragma unroll 2
    for (int t = tid; t < CIN*70; t += NTHR) {
        int c = t / 70, i = t - c*70;
        const float2* tr = temp + c*72;
        float2 v0 = tr[i];
        float  xs1 = tr[min(i+1, 69)].y;
        float  xs2 = tr[min(i+2, 69)].y;
        float  xs3 = tr[min(i+3, 69)].y;
        float r1 = rtap(xs1, v0.y);
        float r2 = rtap(xs2, v0.y);
        float r3 = rtap(xs3, v0.y);
        sxr[c*72 + i] = make_uint2(packh(r1, r2), packh(r3, v0.x));
    }
    __syncthreads();                    // sxr ready; temp dead

    build_m(smem + OFF_ST, 0, tid, sxr);
    CPWAIT0();
    __syncthreads();                    // stage 0 ready

    const int m0 = (wid & 3) * 32;      // o offset (4 warps across o)
    const int n0 = (wid >> 2) * 16;     // l offset (4 warps across l)
    const uint32_t laneA = (uint32_t)((lane & 15)*ROWB + ((lane >> 4) & 1)*16);
    const uint32_t laneB = (uint32_t)(((lane & 7) + 8*((lane >> 4) & 1))*ROWB + ((lane >> 3) & 1)*16);

    float acc[2][2][4];
    #pragma unroll
    for (int i = 0; i < 2; ++i)
        #pragma unroll
        for (int n = 0; n < 2; ++n)
            #pragma unroll
            for (int r = 0; r < 4; ++r) acc[i][n][r] = 0.f;

    #pragma unroll 1
    for (int ch = 0; ch < NCH; ++ch) {
        const int s = ch & 1;
        const uint32_t stc = sb + (uint32_t)(OFF_ST + s*STAGE_BYTES);
        if (ch + 1 < NCH) {
            load_w(sb + (uint32_t)(OFF_ST + (s^1)*STAGE_BYTES), ch + 1, tid);
            build_m(smem + OFF_ST + (s^1)*STAGE_BYTES, ch + 1, tid, sxr);
        }
        const uint32_t aW0 = stc + T_W + (uint32_t)m0*ROWB + laneA;
        const uint32_t bM0 = stc + T_M + (uint32_t)n0*ROWB + laneB;
        #pragma unroll
        for (int ks = 0; ks < 4; ++ks) {
            const uint32_t kb = (uint32_t)(ks * 32);
            uint32_t a[2][4], bm[4];
            LDSM4(a[0], aW0 + kb);
            LDSM4(a[1], aW0 + kb + 16*ROWB);
            LDSM4(bm, bM0 + kb);
            #pragma unroll
            for (int i = 0; i < 2; ++i) {
                #pragma unroll
                for (int n = 0; n < 2; ++n) {
                    const int e = n*2;
                    MMAH(acc[i][n], a[i], bm[e], bm[e+1]);
                }
            }
        }
        if (ch + 1 < NCH) CPWAIT0();
        __syncthreads();
    }

    // ---- epilogue: direct STG.64 ----
    const int g = lane >> 2, tq = lane & 3;
    float* outb = out + (size_t)b*COUT*NN + l0;
    #pragma unroll
    for (int i = 0; i < 2; ++i) {
        int o = m0 + i*16 + g;
        #pragma unroll
        for (int n = 0; n < 2; ++n) {
            int lp = n0 + n*8 + 2*tq;
            *(float2*)(outb + (size_t)o*NN + lp)     = make_float2(acc[i][n][0], acc[i][n][1]);
            *(float2*)(outb + (size_t)(o+8)*NN + lp) = make_float2(acc[i][n][2], acc[i][n][3]);
        }
    }
}

// ---------------- launch ----------------
extern "C" void kernel_launch(void* const* d_in, const int* in_sizes, int n_in,
                              void* d_out, int out_size) {
    const float* deep   = (const float*)d_in[0];
    const float* x      = (const float*)d_in[1];
    const float* conv_w = (const float*)d_in[2];
    const float* conv_b = (const float*)d_in[3];
    const float* fc_w   = (const float*)d_in[4];
    float* out = (float*)d_out;

    cudaFuncSetAttribute(k_tc, cudaFuncAttributeMaxDynamicSharedMemorySize, SMEM_TOTAL);

    k_prep<<<BB*CIN, 256>>>(deep, conv_w, conv_b, fc_w);
    k_tc  <<<dim3(NN/LT, BB), NTHR, SMEM_TOTAL>>>(x, conv_b, out);
}